// round 16
// baseline (speedup 1.0000x reference)
#include <cuda_runtime.h>
#include <cuda_bf16.h>
#include <cuda_fp16.h>
#include <cstdint>

// ============================================================================
// 4-layer pyramidal BiGRU. B=32, H=512, 3H=1536.
// Layers l=0..3: T = 1024,512,256,128 ; din = 240,2048,2048,2048
// fp16 tensor math (A/h single, W hi+lo 2-term), fp32 carry/epilogue.
// ============================================================================

#define REC_THREADS 256

// ---------------- static device scratch ----------------
__device__ float g_xzf[50331648];                 // [32][1024][1536] max
__device__ float g_xzb[50331648];
__device__ unsigned int g_flag[1024];             // [dir][64 ctas][8 warps]
__device__ unsigned char g_mask[65536];           // per-layer offsets
__device__ __half g_wh[19611648], g_wl[19611648]; // weights fp16 hi/lo
__device__ __half g_in[7864320];                  // input fp16 [32*1024][240]
__device__ __half g_y0[33554432];                 // [32][1024][1024] fp16
__device__ __half g_y1[16777216];                 // [32][512][1024] fp16
__device__ __half g_hh[4 * 16384];                // [parity][dir][32][512]

// ---------------- mma / ldmatrix ----------------
#define MMA_F16(c, a, b0, b1)                                               \
    asm volatile("mma.sync.aligned.m16n8k16.row.col.f32.f16.f16.f32 "       \
        "{%0,%1,%2,%3}, {%4,%5,%6,%7}, {%8,%9}, {%0,%1,%2,%3};"             \
        : "+f"((c)[0]), "+f"((c)[1]), "+f"((c)[2]), "+f"((c)[3])            \
        : "r"((a)[0]), "r"((a)[1]), "r"((a)[2]), "r"((a)[3]),               \
          "r"(b0), "r"(b1))

#define LDSM4(R, addr)                                                      \
    asm volatile("ldmatrix.sync.aligned.m8n8.x4.shared.b16 "                \
        "{%0,%1,%2,%3}, [%4];"                                              \
        : "=r"((R)[0]), "=r"((R)[1]), "=r"((R)[2]), "=r"((R)[3])            \
        : "r"(addr))

#define LDSM4T(R, addr)                                                     \
    asm volatile("ldmatrix.sync.aligned.m8n8.x4.trans.shared.b16 "          \
        "{%0,%1,%2,%3}, [%4];"                                              \
        : "=r"((R)[0]), "=r"((R)[1]), "=r"((R)[2]), "=r"((R)[3])            \
        : "r"(addr))

__device__ __forceinline__ unsigned int smaddr(const void* p) {
    return (unsigned int)__cvta_generic_to_shared(p);
}
__device__ __forceinline__ unsigned int h2pack(float a, float b) {
    __half2 h = __floats2half2_rn(a, b);
    return *reinterpret_cast<unsigned int*>(&h);
}

// ============================================================================
// prep kernel: weights -> fp16 hi/lo; input -> fp16; layer-0 mask; flags.
// ============================================================================
__device__ __forceinline__ void cvt4h(float4 v, uint2& hi, uint2& lo) {
    __half2 h0 = __floats2half2_rn(v.x, v.y);
    __half2 h1 = __floats2half2_rn(v.z, v.w);
    float2 f0 = __half22float2(h0);
    float2 f1 = __half22float2(h1);
    __half2 l0 = __floats2half2_rn(v.x - f0.x, v.y - f0.y);
    __half2 l1 = __floats2half2_rn(v.z - f1.x, v.w - f1.y);
    hi.x = *(unsigned int*)&h0; hi.y = *(unsigned int*)&h1;
    lo.x = *(unsigned int*)&l0; lo.y = *(unsigned int*)&l1;
}

#define WSZ0 368640
#define WSZ1 3145728

__global__ void prep_kernel(const float* __restrict__ in,
                            const float* w0, const float* w1, const float* w2,
                            const float* w3, const float* w4, const float* w5,
                            const float* w6, const float* w7) {
    const float* ws[8] = {w0, w1, w2, w3, w4, w5, w6, w7};
    const int sz[8]  = {WSZ0, WSZ0, WSZ1, WSZ1, WSZ1, WSZ1, WSZ1, WSZ1};
    const int off[8] = {0, WSZ0, 2 * WSZ0, 2 * WSZ0 + WSZ1, 2 * WSZ0 + 2 * WSZ1,
                        2 * WSZ0 + 3 * WSZ1, 2 * WSZ0 + 4 * WSZ1, 2 * WSZ0 + 5 * WSZ1};
    const int gid = blockIdx.x * blockDim.x + threadIdx.x;
    const int stride = gridDim.x * blockDim.x;

    #pragma unroll 1
    for (int w = 0; w < 8; ++w) {
        const float4* W = (const float4*)ws[w];
        uint2* hi = (uint2*)(g_wh + off[w]);
        uint2* lo = (uint2*)(g_wl + off[w]);
        int n4 = sz[w] >> 2;
        for (int i = gid; i < n4; i += stride) {
            uint2 h, l; cvt4h(__ldg(W + i), h, l);
            hi[i] = h; lo[i] = l;
        }
    }
    {
        const float4* X = (const float4*)in;
        uint2* dst = (uint2*)g_in;
        for (int i = gid; i < (7864320 >> 2); i += stride) {
            float4 v = __ldg(X + i);
            __half2 h0 = __floats2half2_rn(v.x, v.y);
            __half2 h1 = __floats2half2_rn(v.z, v.w);
            uint2 o = {*(unsigned int*)&h0, *(unsigned int*)&h1};
            dst[i] = o;
        }
    }
    for (int r = gid; r < 32768; r += stride) {
        const float4* p = (const float4*)(in + (size_t)r * 240);
        bool any = false;
        for (int i = 0; i < 60; ++i) {
            float4 v = __ldg(p + i);
            any = any | (v.x != 0.f) | (v.y != 0.f) | (v.z != 0.f) | (v.w != 0.f);
            if (any) break;
        }
        g_mask[r] = any ? 1 : 0;
    }
    for (int i = gid; i < 1024; i += stride) g_flag[i] = 0u;
}

// ============================================================================
// Input-projection GEMM — EXACT round-15 version (proven best):
// fp16 A (single) x fp16 W (hi+lo), tile 128x128x16, 2 CTAs/SM, mask skip.
// ============================================================================
__global__ void __launch_bounds__(256, 2) gemm_xz(
    const __half* __restrict__ A, int lda,
    const __half* __restrict__ WhF, const __half* __restrict__ WlF,
    const __half* __restrict__ WhB, const __half* __restrict__ WlB,
    const float* __restrict__ biasF, const float* __restrict__ biasB,
    float* __restrict__ Cf, float* __restrict__ Cb,
    int K, int Tcur, const unsigned char* __restrict__ mask) {
    __shared__ __align__(16) __half a_s[128 * 24];
    __shared__ __align__(16) __half w_hi[16 * 136], w_lo[16 * 136];

    const int dir = blockIdx.z;
    const int rev = dir;
    const __half* Wh = dir ? WhB : WhF;
    const __half* Wl = dir ? WlB : WlF;
    const float* bias = dir ? biasB : biasF;
    float* C = dir ? Cb : Cf;

    const int tid  = threadIdx.x;
    const int lane = tid & 31, wid = tid >> 5;
    const int g = lane >> 2, t4 = lane & 3;
    const int warpM = wid & 3, warpN = wid >> 2;
    const int m0 = blockIdx.y << 7, n0 = blockIdx.x << 7;

    {
        const int b  = m0 / Tcur;
        const int t0 = m0 - b * Tcur;
        const int ttmin = rev ? (Tcur - 128 - t0) : t0;
        if (mask[b * Tcur + ttmin] == 0) return;
    }

    const int ar = tid >> 1;
    const int ak = (tid & 1) << 3;
    const int wk = tid >> 4;
    const int wc = (tid & 15) << 3;

    const __half* pA;
    {
        int m  = m0 + ar;
        int bi = m / Tcur;
        int t  = m - bi * Tcur;
        int tt = rev ? (Tcur - 1 - t) : t;
        pA = A + ((size_t)bi * Tcur + tt) * lda + ak;
    }
    const __half* pWh = Wh + (size_t)wk * 1536 + n0 + wc;
    const __half* pWl = Wl + (size_t)wk * 1536 + n0 + wc;

    const int aRowL = warpM * 32 + (lane & 15);
    const int aKofL = (lane & 16) >> 1;
    const unsigned int aAddr = smaddr(a_s) + (unsigned)((aRowL * 24 + aKofL) * 2);
    const int bCol = warpN * 64 + ((lane & 16) >> 1);
    const unsigned int bHiAddr = smaddr(w_hi) + (unsigned)(((lane & 15) * 136 + bCol) * 2);
    const unsigned int bLoAddr = smaddr(w_lo) + (unsigned)(((lane & 15) * 136 + bCol) * 2);

    float c_[2][8][4];
    #pragma unroll
    for (int mt = 0; mt < 2; ++mt)
        #pragma unroll
        for (int nt = 0; nt < 8; ++nt)
            #pragma unroll
            for (int i = 0; i < 4; ++i) c_[mt][nt][i] = 0.f;

    const int NT = K >> 4;
    uint4 rA  = *(const uint4*)pA;
    uint4 rWh = *(const uint4*)pWh;
    uint4 rWl = *(const uint4*)pWl;

    for (int kt = 0; kt < NT; ++kt) {
        *(uint4*)(a_s + ar * 24 + ak)   = rA;
        *(uint4*)(w_hi + wk * 136 + wc) = rWh;
        *(uint4*)(w_lo + wk * 136 + wc) = rWl;
        __syncthreads();

        if (kt + 1 < NT) {
            int k0 = (kt + 1) << 4;
            rA  = *(const uint4*)(pA + k0);
            rWh = *(const uint4*)(pWh + (size_t)k0 * 1536);
            rWl = *(const uint4*)(pWl + (size_t)k0 * 1536);
        }

        unsigned int af[2][4];
        #pragma unroll
        for (int mt = 0; mt < 2; ++mt)
            LDSM4(af[mt], aAddr + mt * 768);

        #pragma unroll
        for (int p = 0; p < 4; ++p) {
            unsigned int bh[4], bl[4];
            LDSM4T(bh, bHiAddr + p * 32);
            LDSM4T(bl, bLoAddr + p * 32);
            #pragma unroll
            for (int s = 0; s < 2; ++s) {
                const int nt = 2 * p + s;
                #pragma unroll
                for (int mt = 0; mt < 2; ++mt) {
                    MMA_F16(c_[mt][nt], af[mt], bh[2 * s], bh[2 * s + 1]);
                    MMA_F16(c_[mt][nt], af[mt], bl[2 * s], bl[2 * s + 1]);
                }
            }
        }
        __syncthreads();
    }

    #pragma unroll
    for (int nt = 0; nt < 8; ++nt) {
        int col = n0 + warpN * 64 + nt * 8 + t4 * 2;
        float bx = __ldg(bias + col);
        float by = __ldg(bias + col + 1);
        #pragma unroll
        for (int mt = 0; mt < 2; ++mt) {
            int r = m0 + warpM * 32 + mt * 16 + g;
            float2 o0 = {c_[mt][nt][0] + bx, c_[mt][nt][1] + by};
            float2 o1 = {c_[mt][nt][2] + bx, c_[mt][nt][3] + by};
            *(float2*)(C + (size_t)r * 1536 + col)       = o0;
            *(float2*)(C + (size_t)(r + 8) * 1536 + col) = o1;
        }
    }
}

// ============================================================================
// Recurrence: per-warp dataflow + PER-WARP FLAGS + parity-buffered partials.
//   Producer warp w' publishes flag[dir][j][w'] right after its own 32
//   h-stores (+syncwarp) — no post-epilogue CTA barrier.
//   Consumer warp w polls the contiguous 64-flag window [dir*512+64w .. +64)
//   (its 8 producer CTAs x 8 warps; 2 flags per lane).
//   sh_part is double-buffered by t&1 so warps can run ahead safely; the
//   pre-epilogue join (covers all 64 producers) preserves WAR safety on the
//   h parity buffers.  Fast-math epilogue (__expf-based, err ~1e-6).
// SMEM: ah[32][520] fp16 | part[2][8][3][256] f32 | hp[256] f32  (~83 KB)
// ============================================================================
#define LDK 520
#define REC_SMEM (32 * LDK * 2 + 2 * 8 * 3 * 256 * 4 + 256 * 4)

__global__ void __launch_bounds__(REC_THREADS, 1) gru_rec_kernel(
    const float* __restrict__ xzf, const float* __restrict__ xzb,
    const float* __restrict__ rkf, const float* __restrict__ rkb,
    const float* __restrict__ bf,  const float* __restrict__ bb,
    const unsigned char* __restrict__ mask,
    float* __restrict__ y32,
    __half* __restrict__ yh,
    unsigned char* __restrict__ nextmask,
    int T, int flagBase, int writeHidden, float* __restrict__ hiddenOut) {
    extern __shared__ __align__(16) char smraw[];
    __half* sh_ah = (__half*)smraw;                       // [32][520]
    float* sh_part = (float*)(sh_ah + 32 * LDK);          // [2][8][3][256]
    float* sh_hp   = sh_part + 2 * 8 * 3 * 256;           // [256]

    const int tid  = threadIdx.x;
    const int lane = tid & 31, wid = tid >> 5;
    const int dir = blockIdx.x >> 6;
    const int j   = blockIdx.x & 63;
    const int cb  = j << 3;
    const int b   = tid >> 3;
    const int c8  = tid & 7;
    const int col = cb + c8;

    const float* xz = dir ? xzb : xzf;
    const float* rk = dir ? rkb : rkf;
    const float* bi = (dir ? bb : bf) + 1536;   // b[1]

    sh_hp[tid] = 0.f;

    // ---- B-fragment preload (fp16 hi/lo): warp w owns kt = 4w..4w+3 ----
    const int t4 = lane & 3;
    const int gcol = lane >> 2;
    unsigned int Bh0[3][4], Bh1[3][4], Bl0[3][4], Bl1[3][4];
    #pragma unroll 1
    for (int gate = 0; gate < 3; ++gate) {
        const float* wcolp = rk + gate * 512 + cb + gcol;
        #pragma unroll
        for (int q = 0; q < 4; ++q) {
            int k0 = (wid * 4 + q) * 16 + t4 * 2;
            float w00 = __ldg(wcolp + (size_t)(k0)     * 1536);
            float w01 = __ldg(wcolp + (size_t)(k0 + 1) * 1536);
            float w10 = __ldg(wcolp + (size_t)(k0 + 8) * 1536);
            float w11 = __ldg(wcolp + (size_t)(k0 + 9) * 1536);
            __half h00 = __float2half_rn(w00), h01 = __float2half_rn(w01);
            __half h10 = __float2half_rn(w10), h11 = __float2half_rn(w11);
            Bh0[gate][q] = ((unsigned)*(unsigned short*)&h01 << 16) | *(unsigned short*)&h00;
            Bh1[gate][q] = ((unsigned)*(unsigned short*)&h11 << 16) | *(unsigned short*)&h10;
            Bl0[gate][q] = h2pack(w00 - __half2float(h00), w01 - __half2float(h01));
            Bl1[gate][q] = h2pack(w10 - __half2float(h10), w11 - __half2float(h11));
        }
    }
    const float bz = __ldg(bi + col);
    const float br = __ldg(bi + 512 + col);
    const float bh = __ldg(bi + 1024 + col);
    __syncthreads();

    const unsigned int aB0 = smaddr(sh_ah) +
        (unsigned)((((lane & 15)) * LDK + ((lane >> 4) << 3)) * 2) + (unsigned)(wid * 128);
    const unsigned int aB1 = aB0 + (unsigned)(16 * LDK * 2);

    // per-warp flags: producer (j, wid) -> g_flag[dir*512 + j*8 + wid]
    unsigned int* myflag = g_flag + dir * 512 + j * 8 + wid;
    // consumer warp w: 64-flag window for producers 8w..8w+7 (all warps)
    const unsigned int* pf = g_flag + dir * 512 + wid * 64 + lane;
    const bool maskWriter = (nextmask != nullptr) && (dir == 0) && (j == 0) && (c8 == 0);
    unsigned char mprev = 0;

    for (int t = 0; t < T; ++t) {
        const int tsrc = dir ? (T - 1 - t) : t;
        const size_t xoff = ((size_t)b * T + t) * 1536;
        const float x0 = __ldg(xz + xoff + col);
        const float x1 = __ldg(xz + xoff + 512 + col);
        const float x2 = __ldg(xz + xoff + 1024 + col);
        const unsigned char m = mask[b * T + tsrc];
        float* partbuf = sh_part + (t & 1) * (8 * 3 * 256);

        if (t > 0) {
            // ---- per-warp: wait for all 8x8 producer-warp flags ----
            {
                const unsigned int target = (unsigned int)(flagBase + t);
                unsigned int v0, v1;
                do {
                    asm volatile("ld.acquire.gpu.global.u32 %0, [%1];"
                                 : "=r"(v0) : "l"(pf) : "memory");
                    asm volatile("ld.acquire.gpu.global.u32 %0, [%1];"
                                 : "=r"(v1) : "l"(pf + 32) : "memory");
                } while (__any_sync(0xffffffffu, (v0 < target) | (v1 < target)));
            }

            // ---- per-warp: stage own 64-col fp16 chunk (4KB) ----
            const size_t hsrc = (size_t)(((t & 1) * 2 + dir)) << 14;
            const __half* gh = g_hh + hsrc + wid * 64;
            uint4 hv[8];
            #pragma unroll
            for (int q = 0; q < 8; ++q) {
                int v = q * 32 + lane;
                int bb2 = v >> 3, kc = v & 7;
                hv[q] = __ldcg((const uint4*)(gh + (bb2 << 9) + kc * 8));
            }
            #pragma unroll
            for (int q = 0; q < 8; ++q) {
                int v = q * 32 + lane;
                int bb2 = v >> 3, kc = v & 7;
                *(uint4*)(sh_ah + bb2 * LDK + wid * 64 + kc * 8) = hv[q];
            }
            __syncwarp();

            // ---- per-warp mma: 4 kt x (2 LDSM + 12 mma) ----
            float acc[3][2][4];
            #pragma unroll
            for (int gg = 0; gg < 3; ++gg)
                #pragma unroll
                for (int mt = 0; mt < 2; ++mt)
                    #pragma unroll
                    for (int i = 0; i < 4; ++i) acc[gg][mt][i] = 0.f;

            #pragma unroll
            for (int q = 0; q < 4; ++q) {
                unsigned int ah[2][4];
                LDSM4(ah[0], aB0 + q * 32);
                LDSM4(ah[1], aB1 + q * 32);
                #pragma unroll
                for (int gg = 0; gg < 3; ++gg) {
                    #pragma unroll
                    for (int mt = 0; mt < 2; ++mt) {
                        MMA_F16(acc[gg][mt], ah[mt], Bh0[gg][q], Bh1[gg][q]);
                        MMA_F16(acc[gg][mt], ah[mt], Bl0[gg][q], Bl1[gg][q]);
                    }
                }
            }
            const int row = lane >> 2, cq = (lane & 3) << 1;
            #pragma unroll
            for (int gg = 0; gg < 3; ++gg) {
                #pragma unroll
                for (int mt = 0; mt < 2; ++mt) {
                    float* gp = partbuf + (wid * 3 + gg) * 256 + (mt * 16 + row) * 8 + cq;
                    gp[0]  = acc[gg][mt][0];
                    gp[1]  = acc[gg][mt][1];
                    gp[64] = acc[gg][mt][2];
                    gp[65] = acc[gg][mt][3];
                }
            }
            __syncthreads();   // join: all 64 producers' effects visible
        }

        // ---- scalar epilogue (fast math) ----
        float iz = bz, ir = br, ic = bh;
        if (t > 0) {
            #pragma unroll
            for (int w = 0; w < 8; ++w) {
                iz += partbuf[(w * 3 + 0) * 256 + tid];
                ir += partbuf[(w * 3 + 1) * 256 + tid];
                ic += partbuf[(w * 3 + 2) * 256 + tid];
            }
        }

        const float zg = __fdividef(1.f, 1.f + __expf(-(x0 + iz)));
        const float rg = __fdividef(1.f, 1.f + __expf(-(x1 + ir)));
        const float ta = x2 + rg * ic;
        const float hh = 1.f - __fdividef(2.f, 1.f + __expf(2.f * ta));
        const float hp = sh_hp[tid];
        const float hn = zg * hp + (1.f - zg) * hh;
        const float hsel = m ? hn : hp;
        const float yval = m ? hn : 0.f;
        sh_hp[tid] = hsel;

        // ---- critical path: publish h + per-warp flag ----
        const size_t hdst = (size_t)((((t + 1) & 1) * 2 + dir)) << 14;
        g_hh[hdst + (b << 9) + col] = __float2half_rn(hsel);
        __syncwarp();
        if (lane == 0) {
            unsigned int v = (unsigned int)(flagBase + t + 1);
            asm volatile("st.release.gpu.global.u32 [%0], %1;"
                         :: "l"(myflag), "r"(v) : "memory");
        }

        // ---- off critical path: outputs ----
        const size_t yidx = ((size_t)b * T + tsrc) * 1024 + (dir << 9) + col;
        if (yh) yh[yidx] = __float2half_rn(yval);
        if (y32) y32[yidx] = yval;
        if (writeHidden && t == T - 1)
            hiddenOut[(b << 10) + (dir << 9) + col] = hsel;
        if (maskWriter) {
            if ((t & 1) == 0) mprev = m;
            else nextmask[b * (T >> 1) + (t >> 1)] = (unsigned char)(mprev | m);
        }
    }
}

// ============================================================================
// Launch sequence (graph-capturable)
// ============================================================================
extern "C" void kernel_launch(void* const* d_in, const int* in_sizes, int n_in,
                              void* d_out, int out_size) {
    (void)in_sizes; (void)n_in; (void)out_size;
    const float* inputs = (const float*)d_in[0];

    const float *k_[4][2], *r_[4][2], *bi_[4][2];
    for (int l = 0; l < 4; ++l)
        for (int d = 0; d < 2; ++d) {
            int base = 3 + l * 6 + d * 3;
            k_[l][d]  = (const float*)d_in[base + 0];
            r_[l][d]  = (const float*)d_in[base + 1];
            bi_[l][d] = (const float*)d_in[base + 2];
        }

    float *xzf, *xzb;
    unsigned char* mk;
    __half *wh, *wl, *inh, *y0, *y1;
    cudaGetSymbolAddress((void**)&xzf, g_xzf);
    cudaGetSymbolAddress((void**)&xzb, g_xzb);
    cudaGetSymbolAddress((void**)&mk, g_mask);
    cudaGetSymbolAddress((void**)&wh, g_wh);
    cudaGetSymbolAddress((void**)&wl, g_wl);
    cudaGetSymbolAddress((void**)&inh, g_in);
    cudaGetSymbolAddress((void**)&y0, g_y0);
    cudaGetSymbolAddress((void**)&y1, g_y1);

    cudaFuncSetAttribute(gru_rec_kernel,
                         cudaFuncAttributeMaxDynamicSharedMemorySize, REC_SMEM);

    float* outp = (float*)d_out;
    float* hid  = outp + (size_t)32 * 128 * 1024;

    prep_kernel<<<2048, 256>>>(inputs, k_[0][0], k_[0][1], k_[1][0], k_[1][1],
                               k_[2][0], k_[2][1], k_[3][0], k_[3][1]);

    const int Ts[4]   = {1024, 512, 256, 128};
    const int Ks[4]   = {240, 2048, 2048, 2048};
    const int ldas[4] = {240, 2048, 2048, 2048};
    const int woff[4][2] = {{0, WSZ0},
                            {2 * WSZ0, 2 * WSZ0 + WSZ1},
                            {2 * WSZ0 + 2 * WSZ1, 2 * WSZ0 + 3 * WSZ1},
                            {2 * WSZ0 + 4 * WSZ1, 2 * WSZ0 + 5 * WSZ1}};
    const int moff[4]  = {0, 32768, 49152, 57344};
    const int fbase[4] = {0, 1024, 1536, 1792};

    const __half* Ah[4] = {inh, y0, y1, y0};
    __half* Yh[4] = {y0, y1, y0, nullptr};
    float* Y32[4] = {nullptr, nullptr, nullptr, outp};

    for (int l = 0; l < 4; ++l) {
        const int T = Ts[l], K = Ks[l];
        const int rows = 32 * T;

        dim3 grid(12, rows / 128, 2);
        gemm_xz<<<grid, 256>>>(Ah[l], ldas[l],
                               wh + woff[l][0], wl + woff[l][0],
                               wh + woff[l][1], wl + woff[l][1],
                               bi_[l][0], bi_[l][1],
                               xzf, xzb, K, T, mk + moff[l]);

        gru_rec_kernel<<<128, REC_THREADS, REC_SMEM>>>(
            xzf, xzb, r_[l][0], r_[l][1], bi_[l][0], bi_[l][1],
            mk + moff[l], Y32[l], Yh[l],
            (l < 3) ? (mk + moff[l + 1]) : nullptr,
            T, fbase[l], (l == 3) ? 1 : 0, hid);
    }
}

// round 17
// speedup vs baseline: 1.3796x; 1.3796x over previous
#include <cuda_runtime.h>
#include <cuda_bf16.h>
#include <cuda_fp16.h>
#include <cstdint>

// ============================================================================
// 4-layer pyramidal BiGRU. B=32, H=512, 3H=1536.
// Layers l=0..3: T = 1024,512,256,128 ; din = 240,2048,2048,2048
// fp16 tensor math (A/h single, W hi+lo 2-term), fp32 carry/epilogue.
// Round 17 = round-15 structure (proven 8.43ms) + fast-math epilogue only.
// ============================================================================

#define REC_THREADS 256

// ---------------- static device scratch ----------------
__device__ float g_xzf[50331648];                 // [32][1024][1536] max
__device__ float g_xzb[50331648];
__device__ unsigned int g_flag[2 * 512];          // [dir][64 ctas] stride-8
__device__ unsigned char g_mask[65536];           // per-layer offsets
__device__ __half g_wh[19611648], g_wl[19611648]; // weights fp16 hi/lo
__device__ __half g_in[7864320];                  // input fp16 [32*1024][240]
__device__ __half g_y0[33554432];                 // [32][1024][1024] fp16
__device__ __half g_y1[16777216];                 // [32][512][1024] fp16
__device__ __half g_hh[4 * 16384];                // [parity][dir][32][512]

// ---------------- mma / ldmatrix ----------------
#define MMA_F16(c, a, b0, b1)                                               \
    asm volatile("mma.sync.aligned.m16n8k16.row.col.f32.f16.f16.f32 "       \
        "{%0,%1,%2,%3}, {%4,%5,%6,%7}, {%8,%9}, {%0,%1,%2,%3};"             \
        : "+f"((c)[0]), "+f"((c)[1]), "+f"((c)[2]), "+f"((c)[3])            \
        : "r"((a)[0]), "r"((a)[1]), "r"((a)[2]), "r"((a)[3]),               \
          "r"(b0), "r"(b1))

#define LDSM4(R, addr)                                                      \
    asm volatile("ldmatrix.sync.aligned.m8n8.x4.shared.b16 "                \
        "{%0,%1,%2,%3}, [%4];"                                              \
        : "=r"((R)[0]), "=r"((R)[1]), "=r"((R)[2]), "=r"((R)[3])            \
        : "r"(addr))

#define LDSM4T(R, addr)                                                     \
    asm volatile("ldmatrix.sync.aligned.m8n8.x4.trans.shared.b16 "          \
        "{%0,%1,%2,%3}, [%4];"                                              \
        : "=r"((R)[0]), "=r"((R)[1]), "=r"((R)[2]), "=r"((R)[3])            \
        : "r"(addr))

__device__ __forceinline__ unsigned int smaddr(const void* p) {
    return (unsigned int)__cvta_generic_to_shared(p);
}
__device__ __forceinline__ unsigned int h2pack(float a, float b) {
    __half2 h = __floats2half2_rn(a, b);
    return *reinterpret_cast<unsigned int*>(&h);
}

// ============================================================================
// prep kernel: weights -> fp16 hi/lo; input -> fp16; layer-0 mask; flags.
// ============================================================================
__device__ __forceinline__ void cvt4h(float4 v, uint2& hi, uint2& lo) {
    __half2 h0 = __floats2half2_rn(v.x, v.y);
    __half2 h1 = __floats2half2_rn(v.z, v.w);
    float2 f0 = __half22float2(h0);
    float2 f1 = __half22float2(h1);
    __half2 l0 = __floats2half2_rn(v.x - f0.x, v.y - f0.y);
    __half2 l1 = __floats2half2_rn(v.z - f1.x, v.w - f1.y);
    hi.x = *(unsigned int*)&h0; hi.y = *(unsigned int*)&h1;
    lo.x = *(unsigned int*)&l0; lo.y = *(unsigned int*)&l1;
}

#define WSZ0 368640
#define WSZ1 3145728

__global__ void prep_kernel(const float* __restrict__ in,
                            const float* w0, const float* w1, const float* w2,
                            const float* w3, const float* w4, const float* w5,
                            const float* w6, const float* w7) {
    const float* ws[8] = {w0, w1, w2, w3, w4, w5, w6, w7};
    const int sz[8]  = {WSZ0, WSZ0, WSZ1, WSZ1, WSZ1, WSZ1, WSZ1, WSZ1};
    const int off[8] = {0, WSZ0, 2 * WSZ0, 2 * WSZ0 + WSZ1, 2 * WSZ0 + 2 * WSZ1,
                        2 * WSZ0 + 3 * WSZ1, 2 * WSZ0 + 4 * WSZ1, 2 * WSZ0 + 5 * WSZ1};
    const int gid = blockIdx.x * blockDim.x + threadIdx.x;
    const int stride = gridDim.x * blockDim.x;

    #pragma unroll 1
    for (int w = 0; w < 8; ++w) {
        const float4* W = (const float4*)ws[w];
        uint2* hi = (uint2*)(g_wh + off[w]);
        uint2* lo = (uint2*)(g_wl + off[w]);
        int n4 = sz[w] >> 2;
        for (int i = gid; i < n4; i += stride) {
            uint2 h, l; cvt4h(__ldg(W + i), h, l);
            hi[i] = h; lo[i] = l;
        }
    }
    {
        const float4* X = (const float4*)in;
        uint2* dst = (uint2*)g_in;
        for (int i = gid; i < (7864320 >> 2); i += stride) {
            float4 v = __ldg(X + i);
            __half2 h0 = __floats2half2_rn(v.x, v.y);
            __half2 h1 = __floats2half2_rn(v.z, v.w);
            uint2 o = {*(unsigned int*)&h0, *(unsigned int*)&h1};
            dst[i] = o;
        }
    }
    for (int r = gid; r < 32768; r += stride) {
        const float4* p = (const float4*)(in + (size_t)r * 240);
        bool any = false;
        for (int i = 0; i < 60; ++i) {
            float4 v = __ldg(p + i);
            any = any | (v.x != 0.f) | (v.y != 0.f) | (v.z != 0.f) | (v.w != 0.f);
            if (any) break;
        }
        g_mask[r] = any ? 1 : 0;
    }
    for (int i = gid; i < 2 * 512; i += stride) g_flag[i] = 0u;
}

// ============================================================================
// Input-projection GEMM — EXACT round-15 version (proven best):
// fp16 A (single) x fp16 W (hi+lo), tile 128x128x16, 2 CTAs/SM, mask skip.
// ============================================================================
__global__ void __launch_bounds__(256, 2) gemm_xz(
    const __half* __restrict__ A, int lda,
    const __half* __restrict__ WhF, const __half* __restrict__ WlF,
    const __half* __restrict__ WhB, const __half* __restrict__ WlB,
    const float* __restrict__ biasF, const float* __restrict__ biasB,
    float* __restrict__ Cf, float* __restrict__ Cb,
    int K, int Tcur, const unsigned char* __restrict__ mask) {
    __shared__ __align__(16) __half a_s[128 * 24];
    __shared__ __align__(16) __half w_hi[16 * 136], w_lo[16 * 136];

    const int dir = blockIdx.z;
    const int rev = dir;
    const __half* Wh = dir ? WhB : WhF;
    const __half* Wl = dir ? WlB : WlF;
    const float* bias = dir ? biasB : biasF;
    float* C = dir ? Cb : Cf;

    const int tid  = threadIdx.x;
    const int lane = tid & 31, wid = tid >> 5;
    const int g = lane >> 2, t4 = lane & 3;
    const int warpM = wid & 3, warpN = wid >> 2;
    const int m0 = blockIdx.y << 7, n0 = blockIdx.x << 7;

    {
        const int b  = m0 / Tcur;
        const int t0 = m0 - b * Tcur;
        const int ttmin = rev ? (Tcur - 128 - t0) : t0;
        if (mask[b * Tcur + ttmin] == 0) return;
    }

    const int ar = tid >> 1;
    const int ak = (tid & 1) << 3;
    const int wk = tid >> 4;
    const int wc = (tid & 15) << 3;

    const __half* pA;
    {
        int m  = m0 + ar;
        int bi = m / Tcur;
        int t  = m - bi * Tcur;
        int tt = rev ? (Tcur - 1 - t) : t;
        pA = A + ((size_t)bi * Tcur + tt) * lda + ak;
    }
    const __half* pWh = Wh + (size_t)wk * 1536 + n0 + wc;
    const __half* pWl = Wl + (size_t)wk * 1536 + n0 + wc;

    const int aRowL = warpM * 32 + (lane & 15);
    const int aKofL = (lane & 16) >> 1;
    const unsigned int aAddr = smaddr(a_s) + (unsigned)((aRowL * 24 + aKofL) * 2);
    const int bCol = warpN * 64 + ((lane & 16) >> 1);
    const unsigned int bHiAddr = smaddr(w_hi) + (unsigned)(((lane & 15) * 136 + bCol) * 2);
    const unsigned int bLoAddr = smaddr(w_lo) + (unsigned)(((lane & 15) * 136 + bCol) * 2);

    float c_[2][8][4];
    #pragma unroll
    for (int mt = 0; mt < 2; ++mt)
        #pragma unroll
        for (int nt = 0; nt < 8; ++nt)
            #pragma unroll
            for (int i = 0; i < 4; ++i) c_[mt][nt][i] = 0.f;

    const int NT = K >> 4;
    uint4 rA  = *(const uint4*)pA;
    uint4 rWh = *(const uint4*)pWh;
    uint4 rWl = *(const uint4*)pWl;

    for (int kt = 0; kt < NT; ++kt) {
        *(uint4*)(a_s + ar * 24 + ak)   = rA;
        *(uint4*)(w_hi + wk * 136 + wc) = rWh;
        *(uint4*)(w_lo + wk * 136 + wc) = rWl;
        __syncthreads();

        if (kt + 1 < NT) {
            int k0 = (kt + 1) << 4;
            rA  = *(const uint4*)(pA + k0);
            rWh = *(const uint4*)(pWh + (size_t)k0 * 1536);
            rWl = *(const uint4*)(pWl + (size_t)k0 * 1536);
        }

        unsigned int af[2][4];
        #pragma unroll
        for (int mt = 0; mt < 2; ++mt)
            LDSM4(af[mt], aAddr + mt * 768);

        #pragma unroll
        for (int p = 0; p < 4; ++p) {
            unsigned int bh[4], bl[4];
            LDSM4T(bh, bHiAddr + p * 32);
            LDSM4T(bl, bLoAddr + p * 32);
            #pragma unroll
            for (int s = 0; s < 2; ++s) {
                const int nt = 2 * p + s;
                #pragma unroll
                for (int mt = 0; mt < 2; ++mt) {
                    MMA_F16(c_[mt][nt], af[mt], bh[2 * s], bh[2 * s + 1]);
                    MMA_F16(c_[mt][nt], af[mt], bl[2 * s], bl[2 * s + 1]);
                }
            }
        }
        __syncthreads();
    }

    #pragma unroll
    for (int nt = 0; nt < 8; ++nt) {
        int col = n0 + warpN * 64 + nt * 8 + t4 * 2;
        float bx = __ldg(bias + col);
        float by = __ldg(bias + col + 1);
        #pragma unroll
        for (int mt = 0; mt < 2; ++mt) {
            int r = m0 + warpM * 32 + mt * 16 + g;
            float2 o0 = {c_[mt][nt][0] + bx, c_[mt][nt][1] + by};
            float2 o1 = {c_[mt][nt][2] + bx, c_[mt][nt][3] + by};
            *(float2*)(C + (size_t)r * 1536 + col)       = o0;
            *(float2*)(C + (size_t)(r + 8) * 1536 + col) = o1;
        }
    }
}

// ============================================================================
// Recurrence — round-15 structure (per-warp dataflow, per-CTA flags, single
// fp16 h / y), plus fast-math epilogue (__expf-based, err ~1e-6).
// SMEM: ah[32][520] fp16 | part[8][3][256] f32 | hp[256] f32
// ============================================================================
#define LDK 520
#define REC_SMEM (32 * LDK * 2 + 8 * 3 * 256 * 4 + 256 * 4)

__global__ void __launch_bounds__(REC_THREADS, 1) gru_rec_kernel(
    const float* __restrict__ xzf, const float* __restrict__ xzb,
    const float* __restrict__ rkf, const float* __restrict__ rkb,
    const float* __restrict__ bf,  const float* __restrict__ bb,
    const unsigned char* __restrict__ mask,
    float* __restrict__ y32,
    __half* __restrict__ yh,
    unsigned char* __restrict__ nextmask,
    int T, int flagBase, int writeHidden, float* __restrict__ hiddenOut) {
    extern __shared__ __align__(16) char smraw[];
    __half* sh_ah = (__half*)smraw;                       // [32][520]
    float* sh_part = (float*)(sh_ah + 32 * LDK);          // [8][3][256]
    float* sh_hp   = sh_part + 8 * 3 * 256;               // [256]

    const int tid  = threadIdx.x;
    const int lane = tid & 31, wid = tid >> 5;
    const int dir = blockIdx.x >> 6;
    const int j   = blockIdx.x & 63;
    const int cb  = j << 3;
    const int b   = tid >> 3;
    const int c8  = tid & 7;
    const int col = cb + c8;

    const float* xz = dir ? xzb : xzf;
    const float* rk = dir ? rkb : rkf;
    const float* bi = (dir ? bb : bf) + 1536;   // b[1]

    sh_hp[tid] = 0.f;

    // ---- B-fragment preload (fp16 hi/lo): warp w owns kt = 4w..4w+3 ----
    const int t4 = lane & 3;
    const int gcol = lane >> 2;
    unsigned int Bh0[3][4], Bh1[3][4], Bl0[3][4], Bl1[3][4];
    #pragma unroll 1
    for (int gate = 0; gate < 3; ++gate) {
        const float* wcolp = rk + gate * 512 + cb + gcol;
        #pragma unroll
        for (int q = 0; q < 4; ++q) {
            int k0 = (wid * 4 + q) * 16 + t4 * 2;
            float w00 = __ldg(wcolp + (size_t)(k0)     * 1536);
            float w01 = __ldg(wcolp + (size_t)(k0 + 1) * 1536);
            float w10 = __ldg(wcolp + (size_t)(k0 + 8) * 1536);
            float w11 = __ldg(wcolp + (size_t)(k0 + 9) * 1536);
            __half h00 = __float2half_rn(w00), h01 = __float2half_rn(w01);
            __half h10 = __float2half_rn(w10), h11 = __float2half_rn(w11);
            Bh0[gate][q] = ((unsigned)*(unsigned short*)&h01 << 16) | *(unsigned short*)&h00;
            Bh1[gate][q] = ((unsigned)*(unsigned short*)&h11 << 16) | *(unsigned short*)&h10;
            Bl0[gate][q] = h2pack(w00 - __half2float(h00), w01 - __half2float(h01));
            Bl1[gate][q] = h2pack(w10 - __half2float(h10), w11 - __half2float(h11));
        }
    }
    const float bz = __ldg(bi + col);
    const float br = __ldg(bi + 512 + col);
    const float bh = __ldg(bi + 1024 + col);
    __syncthreads();

    const unsigned int aB0 = smaddr(sh_ah) +
        (unsigned)((((lane & 15)) * LDK + ((lane >> 4) << 3)) * 2) + (unsigned)(wid * 128);
    const unsigned int aB1 = aB0 + (unsigned)(16 * LDK * 2);

    unsigned int* myflag = g_flag + dir * 512 + j * 8;
    const unsigned int* pollflag = g_flag + dir * 512 + (wid * 8 + (lane & 7)) * 8;
    const bool maskWriter = (nextmask != nullptr) && (dir == 0) && (j == 0) && (c8 == 0);
    unsigned char mprev = 0;

    for (int t = 0; t < T; ++t) {
        const int tsrc = dir ? (T - 1 - t) : t;
        const size_t xoff = ((size_t)b * T + t) * 1536;
        const float x0 = __ldg(xz + xoff + col);
        const float x1 = __ldg(xz + xoff + 512 + col);
        const float x2 = __ldg(xz + xoff + 1024 + col);
        const unsigned char m = mask[b * T + tsrc];

        if (t > 0) {
            // ---- per-warp: wait for THIS warp's 8 producer CTAs ----
            {
                const unsigned int target = (unsigned int)(flagBase + t);
                unsigned int v;
                do {
                    asm volatile("ld.acquire.gpu.global.u32 %0, [%1];"
                                 : "=r"(v) : "l"(pollflag) : "memory");
                } while (__any_sync(0xffffffffu, v < target));
            }

            // ---- per-warp: stage own 64-col fp16 chunk (4KB) ----
            const size_t hsrc = (size_t)(((t & 1) * 2 + dir)) << 14;
            const __half* gh = g_hh + hsrc + wid * 64;
            uint4 hv[8];
            #pragma unroll
            for (int q = 0; q < 8; ++q) {
                int v = q * 32 + lane;
                int bb2 = v >> 3, kc = v & 7;
                hv[q] = __ldcg((const uint4*)(gh + (bb2 << 9) + kc * 8));
            }
            #pragma unroll
            for (int q = 0; q < 8; ++q) {
                int v = q * 32 + lane;
                int bb2 = v >> 3, kc = v & 7;
                *(uint4*)(sh_ah + bb2 * LDK + wid * 64 + kc * 8) = hv[q];
            }
            __syncwarp();

            // ---- per-warp mma: 4 kt x (2 LDSM + 12 mma) ----
            float acc[3][2][4];
            #pragma unroll
            for (int gg = 0; gg < 3; ++gg)
                #pragma unroll
                for (int mt = 0; mt < 2; ++mt)
                    #pragma unroll
                    for (int i = 0; i < 4; ++i) acc[gg][mt][i] = 0.f;

            #pragma unroll
            for (int q = 0; q < 4; ++q) {
                unsigned int ah[2][4];
                LDSM4(ah[0], aB0 + q * 32);
                LDSM4(ah[1], aB1 + q * 32);
                #pragma unroll
                for (int gg = 0; gg < 3; ++gg) {
                    #pragma unroll
                    for (int mt = 0; mt < 2; ++mt) {
                        MMA_F16(acc[gg][mt], ah[mt], Bh0[gg][q], Bh1[gg][q]);
                        MMA_F16(acc[gg][mt], ah[mt], Bl0[gg][q], Bl1[gg][q]);
                    }
                }
            }
            const int row = lane >> 2, cq = (lane & 3) << 1;
            #pragma unroll
            for (int gg = 0; gg < 3; ++gg) {
                #pragma unroll
                for (int mt = 0; mt < 2; ++mt) {
                    float* gp = sh_part + (wid * 3 + gg) * 256 + (mt * 16 + row) * 8 + cq;
                    gp[0]  = acc[gg][mt][0];
                    gp[1]  = acc[gg][mt][1];
                    gp[64] = acc[gg][mt][2];
                    gp[65] = acc[gg][mt][3];
                }
            }
            __syncthreads();   // join
        }

        // ---- scalar epilogue (fast math) ----
        float iz = bz, ir = br, ic = bh;
        if (t > 0) {
            #pragma unroll
            for (int w = 0; w < 8; ++w) {
                iz += sh_part[(w * 3 + 0) * 256 + tid];
                ir += sh_part[(w * 3 + 1) * 256 + tid];
                ic += sh_part[(w * 3 + 2) * 256 + tid];
            }
        }

        const float zg = __fdividef(1.f, 1.f + __expf(-(x0 + iz)));
        const float rg = __fdividef(1.f, 1.f + __expf(-(x1 + ir)));
        const float ta = x2 + rg * ic;
        const float hh = 1.f - __fdividef(2.f, 1.f + __expf(2.f * ta));
        const float hp = sh_hp[tid];
        const float hn = zg * hp + (1.f - zg) * hh;
        const float hsel = m ? hn : hp;
        const float yval = m ? hn : 0.f;
        sh_hp[tid] = hsel;

        // ---- critical path: publish h (single fp16) + flag ----
        const size_t hdst = (size_t)((((t + 1) & 1) * 2 + dir)) << 14;
        g_hh[hdst + (b << 9) + col] = __float2half_rn(hsel);
        __syncthreads();
        if (tid == 0) {
            unsigned int v = (unsigned int)(flagBase + t + 1);
            asm volatile("st.release.gpu.global.u32 [%0], %1;"
                         :: "l"(myflag), "r"(v) : "memory");
        }

        // ---- off critical path: outputs ----
        const size_t yidx = ((size_t)b * T + tsrc) * 1024 + (dir << 9) + col;
        if (yh) yh[yidx] = __float2half_rn(yval);
        if (y32) y32[yidx] = yval;
        if (writeHidden && t == T - 1)
            hiddenOut[(b << 10) + (dir << 9) + col] = hsel;
        if (maskWriter) {
            if ((t & 1) == 0) mprev = m;
            else nextmask[b * (T >> 1) + (t >> 1)] = (unsigned char)(mprev | m);
        }
    }
}

// ============================================================================
// Launch sequence (graph-capturable)
// ============================================================================
extern "C" void kernel_launch(void* const* d_in, const int* in_sizes, int n_in,
                              void* d_out, int out_size) {
    (void)in_sizes; (void)n_in; (void)out_size;
    const float* inputs = (const float*)d_in[0];

    const float *k_[4][2], *r_[4][2], *bi_[4][2];
    for (int l = 0; l < 4; ++l)
        for (int d = 0; d < 2; ++d) {
            int base = 3 + l * 6 + d * 3;
            k_[l][d]  = (const float*)d_in[base + 0];
            r_[l][d]  = (const float*)d_in[base + 1];
            bi_[l][d] = (const float*)d_in[base + 2];
        }

    float *xzf, *xzb;
    unsigned char* mk;
    __half *wh, *wl, *inh, *y0, *y1;
    cudaGetSymbolAddress((void**)&xzf, g_xzf);
    cudaGetSymbolAddress((void**)&xzb, g_xzb);
    cudaGetSymbolAddress((void**)&mk, g_mask);
    cudaGetSymbolAddress((void**)&wh, g_wh);
    cudaGetSymbolAddress((void**)&wl, g_wl);
    cudaGetSymbolAddress((void**)&inh, g_in);
    cudaGetSymbolAddress((void**)&y0, g_y0);
    cudaGetSymbolAddress((void**)&y1, g_y1);

    cudaFuncSetAttribute(gru_rec_kernel,
                         cudaFuncAttributeMaxDynamicSharedMemorySize, REC_SMEM);

    float* outp = (float*)d_out;
    float* hid  = outp + (size_t)32 * 128 * 1024;

    prep_kernel<<<2048, 256>>>(inputs, k_[0][0], k_[0][1], k_[1][0], k_[1][1],
                               k_[2][0], k_[2][1], k_[3][0], k_[3][1]);

    const int Ts[4]   = {1024, 512, 256, 128};
    const int Ks[4]   = {240, 2048, 2048, 2048};
    const int ldas[4] = {240, 2048, 2048, 2048};
    const int woff[4][2] = {{0, WSZ0},
                            {2 * WSZ0, 2 * WSZ0 + WSZ1},
                            {2 * WSZ0 + 2 * WSZ1, 2 * WSZ0 + 3 * WSZ1},
                            {2 * WSZ0 + 4 * WSZ1, 2 * WSZ0 + 5 * WSZ1}};
    const int moff[4]  = {0, 32768, 49152, 57344};
    const int fbase[4] = {0, 1024, 1536, 1792};

    const __half* Ah[4] = {inh, y0, y1, y0};
    __half* Yh[4] = {y0, y1, y0, nullptr};
    float* Y32[4] = {nullptr, nullptr, nullptr, outp};

    for (int l = 0; l < 4; ++l) {
        const int T = Ts[l], K = Ks[l];
        const int rows = 32 * T;

        dim3 grid(12, rows / 128, 2);
        gemm_xz<<<grid, 256>>>(Ah[l], ldas[l],
                               wh + woff[l][0], wl + woff[l][0],
                               wh + woff[l][1], wl + woff[l][1],
                               bi_[l][0], bi_[l][1],
                               xzf, xzb, K, T, mk + moff[l]);

        gru_rec_kernel<<<128, REC_THREADS, REC_SMEM>>>(
            xzf, xzb, r_[l][0], r_[l][1], bi_[l][0], bi_[l][1],
            mk + moff[l], Y32[l], Yh[l],
            (l < 3) ? (mk + moff[l + 1]) : nullptr,
            T, fbase[l], (l == 3) ? 1 : 0, hid);
    }
}